// round 1
// baseline (speedup 1.0000x reference)
#include <cuda_runtime.h>
#include <math.h>

#define D      1024
#define DF     4096
#define NTOK   257
#define BSZ    64
#define LAYERS 8
#define HEADS  8
#define HD     128
#define MTOK   (BSZ * NTOK)      /* 16448 rows */
#define SLD    264               /* scores leading dim (257 padded) */

// ---------------- scratch (device globals; no runtime allocation) ----------
__device__ float g_t [MTOK * D];
__device__ float g_xn[MTOK * D];
__device__ float g_q [MTOK * D];
__device__ float g_k [MTOK * D];
__device__ float g_v [MTOK * D];
__device__ float g_y [MTOK * D];
__device__ float g_h [(size_t)MTOK * DF];
__device__ float g_s [(size_t)BSZ * HEADS * NTOK * SLD];

// ---------------- generic batched GEMM -------------------------------------
// C = op( alpha * A @ B(+T) [+ bias] [+ Res] )
// OP: 0 = none, 1 = +bias, 2 = +bias +Res(residual, same layout as C), 3 = gelu(.+bias)
// Per-batch offsets: off = (z / m) * s1 + (z % m) * s2   (m=1,s2=0 => linear)
template <int OP, bool TB>
__global__ void __launch_bounds__(256)
gemm_k(const float* __restrict__ A, const float* __restrict__ B,
       const float* __restrict__ bias, const float* __restrict__ Res,
       float* __restrict__ C,
       int M, int N, int K, int lda, int ldb, int ldc,
       long long sA1, long long sA2, int mA,
       long long sB1, long long sB2, int mB,
       long long sC1, long long sC2, int mC,
       float alpha)
{
    const int z = blockIdx.z;
    A += (long long)(z / mA) * sA1 + (long long)(z % mA) * sA2;
    B += (long long)(z / mB) * sB1 + (long long)(z % mB) * sB2;
    long long coff = (long long)(z / mC) * sC1 + (long long)(z % mC) * sC2;
    C += coff;
    if (OP == 2) Res += coff;

    __shared__ float As[8][128];
    __shared__ float Bs[8][128];

    const int tid = threadIdx.x;
    const int tx  = tid & 15;         // 0..15 -> 8 cols each
    const int ty  = tid >> 4;         // 0..15 -> 8 rows each
    const int row0 = blockIdx.y * 128;
    const int col0 = blockIdx.x * 128;

    float acc[8][8];
#pragma unroll
    for (int i = 0; i < 8; i++)
#pragma unroll
        for (int j = 0; j < 8; j++) acc[i][j] = 0.f;

    for (int kt = 0; kt < K; kt += 8) {
        // load A tile 128x8 (store transposed As[k][r])
#pragma unroll
        for (int i = 0; i < 4; i++) {
            int idx = i * 256 + tid;
            int r = idx >> 3, c = idx & 7;
            int gr = row0 + r, gc = kt + c;
            As[c][r] = (gr < M && gc < K) ? A[(long long)gr * lda + gc] : 0.f;
        }
        // load B tile 8x128
#pragma unroll
        for (int i = 0; i < 4; i++) {
            int idx = i * 256 + tid;
            int c, n;
            if (TB) { n = idx >> 3; c = idx & 7; }
            else    { c = idx >> 7; n = idx & 127; }
            int gk = kt + c, gn = col0 + n;
            float v = 0.f;
            if (gk < K && gn < N)
                v = TB ? B[(long long)gn * ldb + gk]
                       : B[(long long)gk * ldb + gn];
            Bs[c][n] = v;
        }
        __syncthreads();
#pragma unroll
        for (int kk = 0; kk < 8; kk++) {
            float a[8], b[8];
#pragma unroll
            for (int i = 0; i < 8; i++) a[i] = As[kk][ty * 8 + i];
#pragma unroll
            for (int j = 0; j < 8; j++) b[j] = Bs[kk][tx * 8 + j];
#pragma unroll
            for (int i = 0; i < 8; i++)
#pragma unroll
                for (int j = 0; j < 8; j++) acc[i][j] = fmaf(a[i], b[j], acc[i][j]);
        }
        __syncthreads();
    }

#pragma unroll
    for (int i = 0; i < 8; i++) {
        int gr = row0 + ty * 8 + i;
        if (gr >= M) continue;
#pragma unroll
        for (int j = 0; j < 8; j++) {
            int gc = col0 + tx * 8 + j;
            if (gc >= N) continue;
            float v = acc[i][j] * alpha;
            if (OP >= 1) v += bias[gc];
            if (OP == 2) v += Res[(long long)gr * ldc + gc];
            if (OP == 3) v = 0.5f * v * (1.f + erff(v * 0.7071067811865475f));
            C[(long long)gr * ldc + gc] = v;
        }
    }
}

// ---------------- LayerNorm: one block (256 thr) per row of 1024 -----------
__global__ void __launch_bounds__(256)
ln_k(const float* __restrict__ X, const float* __restrict__ g,
     const float* __restrict__ b, float* __restrict__ Y)
{
    const long long row = blockIdx.x;
    const float* x = X + row * D;
    const int tid = threadIdx.x;
    float v[4];
    float s = 0.f;
#pragma unroll
    for (int i = 0; i < 4; i++) { v[i] = x[tid + i * 256]; s += v[i]; }

    __shared__ float red[256];
    red[tid] = s; __syncthreads();
    for (int o = 128; o > 0; o >>= 1) {
        if (tid < o) red[tid] += red[tid + o];
        __syncthreads();
    }
    const float mean = red[0] * (1.f / D);
    __syncthreads();

    float sq = 0.f;
#pragma unroll
    for (int i = 0; i < 4; i++) { float d0 = v[i] - mean; sq += d0 * d0; }
    red[tid] = sq; __syncthreads();
    for (int o = 128; o > 0; o >>= 1) {
        if (tid < o) red[tid] += red[tid + o];
        __syncthreads();
    }
    const float rstd = rsqrtf(red[0] * (1.f / D) + 1e-6f);

    float* y = Y + row * D;
#pragma unroll
    for (int i = 0; i < 4; i++) {
        int d0 = tid + i * 256;
        y[d0] = (v[i] - mean) * rstd * g[d0] + b[d0];
    }
}

// ---------------- softmax: one warp per 257-wide row ------------------------
__global__ void __launch_bounds__(256)
softmax_k(float* __restrict__ S)
{
    const int warp = (blockIdx.x * 256 + threadIdx.x) >> 5;
    const int lane = threadIdx.x & 31;
    const int nrows = BSZ * HEADS * NTOK;
    if (warp >= nrows) return;
    const int bh = warp / NTOK, r = warp % NTOK;
    float* p = S + (long long)bh * (NTOK * SLD) + (long long)r * SLD;

    float vals[9];
    float m = -1e30f;
#pragma unroll
    for (int i = 0; i < 9; i++) {
        int c = lane + i * 32;
        vals[i] = (c < NTOK) ? p[c] : -1e30f;
        m = fmaxf(m, vals[i]);
    }
#pragma unroll
    for (int o = 16; o > 0; o >>= 1) m = fmaxf(m, __shfl_xor_sync(0xffffffffu, m, o));

    float s = 0.f;
#pragma unroll
    for (int i = 0; i < 9; i++) { vals[i] = expf(vals[i] - m); s += vals[i]; }
#pragma unroll
    for (int o = 16; o > 0; o >>= 1) s += __shfl_xor_sync(0xffffffffu, s, o);
    const float inv = 1.f / s;
#pragma unroll
    for (int i = 0; i < 9; i++) {
        int c = lane + i * 32;
        if (c < NTOK) p[c] = vals[i] * inv;
    }
}

// ---------------- patch embedding + pos emb ---------------------------------
__global__ void __launch_bounds__(256)
patch_k(const float* __restrict__ x, const float* __restrict__ w,
        const float* __restrict__ cb, const float* __restrict__ pe,
        float* __restrict__ T)
{
    const int p  = blockIdx.x;        // 0 .. B*256-1
    const int b  = p >> 8, pp = p & 255;
    const int py = pp >> 4, px = pp & 15;
    const int tid = threadIdx.x;

    __shared__ float patch[48];
    if (tid < 48) {
        int ky = tid / 12, kx = (tid % 12) / 3, c = tid % 3;
        patch[tid] = x[(((b * 64) + py * 4 + ky) * 64 + (px * 4 + kx)) * 3 + c];
    }
    __syncthreads();

    float acc[4];
#pragma unroll
    for (int i = 0; i < 4; i++) acc[i] = cb[tid + i * 256];
#pragma unroll
    for (int k = 0; k < 48; k++) {
        float pk = patch[k];
#pragma unroll
        for (int i = 0; i < 4; i++)
            acc[i] = fmaf(pk, w[k * D + tid + i * 256], acc[i]);
    }
    long long base = ((long long)(b * NTOK + 1 + pp)) * D;
#pragma unroll
    for (int i = 0; i < 4; i++) {
        int d0 = tid + i * 256;
        T[base + d0] = acc[i] + pe[(long long)(1 + pp) * D + d0];
    }
}

__global__ void __launch_bounds__(256)
cls_k(const float* __restrict__ cls, const float* __restrict__ pe,
      float* __restrict__ T)
{
    const int b = blockIdx.x, tid = threadIdx.x;
#pragma unroll
    for (int i = 0; i < 4; i++) {
        int d0 = tid + i * 256;
        T[(long long)b * NTOK * D + d0] = cls[d0] + pe[d0];
    }
}

__global__ void __launch_bounds__(256)
out_k(const float* __restrict__ T, float* __restrict__ out)
{
    const int b = blockIdx.x, tid = threadIdx.x;
#pragma unroll
    for (int i = 0; i < 4; i++) {
        int d0 = tid + i * 256;
        out[(long long)b * D + d0] = T[(long long)b * NTOK * D + d0];
    }
}

// ---------------- orchestration ---------------------------------------------
extern "C" void kernel_launch(void* const* d_in, const int* in_sizes, int n_in,
                              void* d_out, int out_size)
{
    const float* x        = (const float*)d_in[0];
    const float* conv_w   = (const float*)d_in[1];
    const float* conv_b   = (const float*)d_in[2];
    const float* cls_tok  = (const float*)d_in[3];
    const float* pos_emb  = (const float*)d_in[4];
    const float* ln1_g    = (const float*)d_in[5];
    const float* ln1_b    = (const float*)d_in[6];
    const float* wq       = (const float*)d_in[7];
    const float* wk       = (const float*)d_in[8];
    const float* wv       = (const float*)d_in[9];
    const float* proj_w   = (const float*)d_in[10];
    const float* proj_b   = (const float*)d_in[11];
    const float* ln2_g    = (const float*)d_in[12];
    const float* ln2_b    = (const float*)d_in[13];
    const float* mlp1_w   = (const float*)d_in[14];
    const float* mlp1_b   = (const float*)d_in[15];
    const float* mlp2_w   = (const float*)d_in[16];
    const float* mlp2_b   = (const float*)d_in[17];
    float* out = (float*)d_out;

    float *t, *xn, *q, *k, *v, *y, *h, *s;
    cudaGetSymbolAddress((void**)&t,  g_t);
    cudaGetSymbolAddress((void**)&xn, g_xn);
    cudaGetSymbolAddress((void**)&q,  g_q);
    cudaGetSymbolAddress((void**)&k,  g_k);
    cudaGetSymbolAddress((void**)&v,  g_v);
    cudaGetSymbolAddress((void**)&y,  g_y);
    cudaGetSymbolAddress((void**)&h,  g_h);
    cudaGetSymbolAddress((void**)&s,  g_s);

    const float scale = 0.08838834764831845f;   // 128^-0.5

    // patch embed + cls + pos
    patch_k<<<BSZ * 256, 256>>>(x, conv_w, conv_b, pos_emb, t);
    cls_k<<<BSZ, 256>>>(cls_tok, pos_emb, t);

    const dim3 gD (D  / 128, (MTOK + 127) / 128, 1);   // (8,129)
    const dim3 gDF(DF / 128, (MTOK + 127) / 128, 1);   // (32,129)
    const dim3 gS ((NTOK + 127) / 128, (NTOK + 127) / 128, BSZ * HEADS); // (3,3,512)
    const dim3 gY (1, (NTOK + 127) / 128, BSZ * HEADS);                  // (1,3,512)

    for (int i = 0; i < LAYERS; i++) {
        const float* wq_i = wq + (size_t)i * D * D;
        const float* wk_i = wk + (size_t)i * D * D;
        const float* wv_i = wv + (size_t)i * D * D;
        const float* pw_i = proj_w + (size_t)i * D * D;
        const float* pb_i = proj_b + (size_t)i * D;
        const float* m1w  = mlp1_w + (size_t)i * D * DF;
        const float* m1b  = mlp1_b + (size_t)i * DF;
        const float* m2w  = mlp2_w + (size_t)i * DF * D;
        const float* m2b  = mlp2_b + (size_t)i * D;

        // LN1
        ln_k<<<MTOK, 256>>>(t, ln1_g + (size_t)i * D, ln1_b + (size_t)i * D, xn);

        // Q (scaled), K, V projections
        gemm_k<0, false><<<gD, 256>>>(xn, wq_i, nullptr, nullptr, q,
            MTOK, D, D, D, D, D, 0,0,1, 0,0,1, 0,0,1, scale);
        gemm_k<0, false><<<gD, 256>>>(xn, wk_i, nullptr, nullptr, k,
            MTOK, D, D, D, D, D, 0,0,1, 0,0,1, 0,0,1, 1.f);
        gemm_k<0, false><<<gD, 256>>>(xn, wv_i, nullptr, nullptr, v,
            MTOK, D, D, D, D, D, 0,0,1, 0,0,1, 0,0,1, 1.f);

        // scores = q @ k^T   per (b,h)
        gemm_k<0, true><<<gS, 256>>>(q, k, nullptr, nullptr, s,
            NTOK, NTOK, HD, D, D, SLD,
            (long long)NTOK * D, HD, HEADS,
            (long long)NTOK * D, HD, HEADS,
            (long long)NTOK * SLD, 0, 1, 1.f);

        // softmax
        softmax_k<<<(BSZ * HEADS * NTOK + 7) / 8, 256>>>(s);

        // y = attn @ v   per (b,h)
        gemm_k<0, false><<<gY, 256>>>(s, v, nullptr, nullptr, y,
            NTOK, HD, NTOK, SLD, D, D,
            (long long)NTOK * SLD, 0, 1,
            (long long)NTOK * D, HD, HEADS,
            (long long)NTOK * D, HD, HEADS, 1.f);

        // t = t + y @ proj_w + proj_b
        gemm_k<2, false><<<gD, 256>>>(y, pw_i, pb_i, t, t,
            MTOK, D, D, D, D, D, 0,0,1, 0,0,1, 0,0,1, 1.f);

        // LN2
        ln_k<<<MTOK, 256>>>(t, ln2_g + (size_t)i * D, ln2_b + (size_t)i * D, xn);

        // h = gelu(xn @ mlp1_w + mlp1_b)
        gemm_k<3, false><<<gDF, 256>>>(xn, m1w, m1b, nullptr, h,
            MTOK, DF, D, D, DF, DF, 0,0,1, 0,0,1, 0,0,1, 1.f);

        // t = t + h @ mlp2_w + mlp2_b
        gemm_k<2, false><<<gD, 256>>>(h, m2w, m2b, t, t,
            MTOK, D, DF, DF, D, D, 0,0,1, 0,0,1, 0,0,1, 1.f);
    }

    out_k<<<BSZ, 256>>>(t, out);
}

// round 3
// speedup vs baseline: 3.1644x; 3.1644x over previous
#include <cuda_runtime.h>
#include <cuda_bf16.h>
#include <cstdint>
#include <math.h>

#define D      1024
#define DF     4096
#define NTOK   257
#define BSZ    64
#define LAYERS 8
#define HEADS  8
#define HD     128
#define MTOK   (BSZ * NTOK)      /* 16448 rows */
#define SLD    264               /* scores leading dim */

#define K3D    (3 * D)           /* 3072  */
#define K3F    (3 * DF)          /* 12288 */

// per-layer bf16 weight block offsets (elements)
#define W_QKV   0
#define W_PROJ  (3072LL * 3072)
#define W_M1    (W_PROJ + 1024LL * 3072)
#define W_M2    (W_M1  + 4096LL * 3072)
#define W_LAYER (W_M2  + 1024LL * 12288)

// ---------------- scratch (device globals) ----------------------------------
__device__ float g_t  [MTOK * D];
__device__ float g_xn [MTOK * D];
__device__ float g_qkv[(size_t)MTOK * 3 * D];
__device__ float g_y  [MTOK * D];
__device__ float g_h  [(size_t)MTOK * DF];
__device__ float g_s  [(size_t)BSZ * HEADS * NTOK * SLD];
__device__ __align__(16) __nv_bfloat16 g_abf[(size_t)MTOK * K3F];
__device__ __align__(16) __nv_bfloat16 g_wbf[(size_t)LAYERS * W_LAYER];

// ============================ PTX helpers ====================================
__device__ __forceinline__ uint32_t smem_u32(const void* p) {
    uint32_t a;
    asm("{ .reg .u64 t; cvta.to.shared.u64 t, %1; cvt.u32.u64 %0, t; }"
        : "=r"(a) : "l"(p));
    return a;
}
__device__ __forceinline__ void cpasync16(uint32_t s, const void* g, uint32_t sz) {
    asm volatile("cp.async.cg.shared.global [%0], [%1], 16, %2;"
                 :: "r"(s), "l"(g), "r"(sz) : "memory");
}
__device__ __forceinline__ void ldsm4(uint32_t& r0, uint32_t& r1,
                                      uint32_t& r2, uint32_t& r3, uint32_t a) {
    asm volatile("ldmatrix.sync.aligned.m8n8.x4.shared.b16 {%0,%1,%2,%3}, [%4];"
                 : "=r"(r0), "=r"(r1), "=r"(r2), "=r"(r3) : "r"(a));
}
__device__ __forceinline__ void mma16816(float* d, const uint32_t* a,
                                         const uint32_t* b) {
    asm volatile("mma.sync.aligned.m16n8k16.row.col.f32.bf16.bf16.f32 "
                 "{%0,%1,%2,%3}, {%4,%5,%6,%7}, {%8,%9}, {%0,%1,%2,%3};"
                 : "+f"(d[0]), "+f"(d[1]), "+f"(d[2]), "+f"(d[3])
                 : "r"(a[0]), "r"(a[1]), "r"(a[2]), "r"(a[3]),
                   "r"(b[0]), "r"(b[1]));
}

// ====================== HMMA split-bf16 GEMM =================================
// C[M,N] = A'[M,K3] (bf16, K-major) @ Bt[N,K3]^T (bf16, K-major)
// EPI: 0 = plain, 2 = +bias +Res, 3 = gelu(. + bias)
#define STG_BYTES 32768
#define GEMM_SMEM (3 * STG_BYTES)   /* 98304 */

template <int EPI>
__global__ void __launch_bounds__(256, 2)
gemm_mma(const __nv_bfloat16* __restrict__ A, const __nv_bfloat16* __restrict__ Bw,
         const float* __restrict__ bias, const float* __restrict__ Res,
         float* __restrict__ C, int M, int N, int K3, int ldc)
{
    extern __shared__ char smem[];
    const uint32_t sb = smem_u32(smem);
    const int tid  = threadIdx.x;
    const int wid  = tid >> 5, lane = tid & 31;
    const int wm   = wid & 1, wn = wid >> 1;       // 2 x 4 warp grid
    const int row0 = blockIdx.y * 128, col0 = blockIdx.x * 128;
    const long long rowBy = (long long)K3 * 2;     // bytes per row

    // ---- cp.async addressing ----
    const int ldrow = tid >> 3, ldch = tid & 7;
    const char* gA = (const char*)A  + (long long)(row0 + ldrow) * rowBy + ldch * 16;
    const char* gB = (const char*)Bw + (long long)(col0 + ldrow) * rowBy + ldch * 16;

    auto load_stage = [&](int kt) {
        const uint32_t st = sb + (kt % 3) * STG_BYTES;
        const long long koff = (long long)kt * 128;
#pragma unroll
        for (int i = 0; i < 4; i++) {
            int r = i * 32 + ldrow;
            uint32_t off = (uint32_t)(r * 128 + ((ldch ^ (r & 7)) * 16));
            uint32_t szA = (row0 + r < M) ? 16u : 0u;
            const char* a = szA ? (gA + (long long)i * 32 * rowBy + koff)
                                : (const char*)A;
            cpasync16(st + off, a, szA);
            cpasync16(st + 16384 + off, gB + (long long)i * 32 * rowBy + koff, 16u);
        }
        asm volatile("cp.async.commit_group;" ::: "memory");
    };

    // ---- ldmatrix lane addressing ----
    const int grp = lane >> 3, l8 = lane & 7;
    const int aRowB = wm * 64 + (grp & 1) * 8 + l8;   // + mi*16
    const int aCG   = grp >> 1;                       // k-chunk group
    const int bRowB = wn * 32 + (grp >> 1) * 8 + l8;  // + ni2*16
    const int bCG   = grp & 1;

    float acc[4][4][4];
#pragma unroll
    for (int i = 0; i < 4; i++)
#pragma unroll
        for (int j = 0; j < 4; j++)
#pragma unroll
            for (int r = 0; r < 4; r++) acc[i][j][r] = 0.f;

    const int nkt = K3 / 64;
    load_stage(0);
    load_stage(1);

    for (int kt = 0; kt < nkt; kt++) {
        asm volatile("cp.async.wait_group 1;" ::: "memory");
        __syncthreads();
        if (kt + 2 < nkt) load_stage(kt + 2);
        else asm volatile("cp.async.commit_group;" ::: "memory");

        const uint32_t sA = sb + (kt % 3) * STG_BYTES;
        const uint32_t sB = sA + 16384;

#pragma unroll
        for (int ks = 0; ks < 4; ks++) {
            uint32_t af[4][4], bf[2][4];
            const uint32_t aSw = (uint32_t)(((ks * 2 + aCG) ^ l8) * 16);
            const uint32_t bSw = (uint32_t)(((ks * 2 + bCG) ^ l8) * 16);
#pragma unroll
            for (int mi = 0; mi < 4; mi++)
                ldsm4(af[mi][0], af[mi][1], af[mi][2], af[mi][3],
                      sA + (uint32_t)((aRowB + mi * 16) * 128) + aSw);
#pragma unroll
            for (int ni2 = 0; ni2 < 2; ni2++)
                ldsm4(bf[ni2][0], bf[ni2][1], bf[ni2][2], bf[ni2][3],
                      sB + (uint32_t)((bRowB + ni2 * 16) * 128) + bSw);
#pragma unroll
            for (int mi = 0; mi < 4; mi++)
#pragma unroll
                for (int ni = 0; ni < 4; ni++)
                    mma16816(acc[mi][ni], af[mi], &bf[ni >> 1][(ni & 1) * 2]);
        }
    }

    // ---- epilogue: direct float2 stores ----
#pragma unroll
    for (int mi = 0; mi < 4; mi++) {
#pragma unroll
        for (int ni = 0; ni < 4; ni++) {
            float* c = acc[mi][ni];
            int m0 = row0 + wm * 64 + mi * 16 + (lane >> 2);
            int n  = col0 + wn * 32 + ni * 8 + (lane & 3) * 2;
            float b0 = 0.f, b1 = 0.f;
            if (EPI >= 2) { b0 = bias[n]; b1 = bias[n + 1]; }
#pragma unroll
            for (int half = 0; half < 2; half++) {
                int m = m0 + half * 8;
                if (m >= M) continue;
                float v0 = c[half * 2 + 0], v1 = c[half * 2 + 1];
                if (EPI == 2) {
                    const float* rp = Res + (size_t)m * ldc + n;
                    v0 += b0 + rp[0]; v1 += b1 + rp[1];
                }
                if (EPI == 3) {
                    v0 += b0; v1 += b1;
                    v0 = 0.5f * v0 * (1.f + erff(v0 * 0.7071067811865475f));
                    v1 = 0.5f * v1 * (1.f + erff(v1 * 0.7071067811865475f));
                }
                *(float2*)(C + (size_t)m * ldc + n) = make_float2(v0, v1);
            }
        }
    }
}

// ====================== split-bf16 conversions ===============================
__global__ void __launch_bounds__(256)
cvtA_k(const float* __restrict__ X, __nv_bfloat16* __restrict__ Aq,
       int K, long long total4)
{
    long long i = (long long)blockIdx.x * 256 + threadIdx.x;
    if (i >= total4) return;
    const int kq = K >> 2;
    long long m = i / kq;
    int k4 = (int)(i % kq) * 4;
    float4 x = ((const float4*)X)[i];

    __nv_bfloat16 h0 = __float2bfloat16(x.x), h1 = __float2bfloat16(x.y);
    __nv_bfloat16 h2 = __float2bfloat16(x.z), h3 = __float2bfloat16(x.w);
    __nv_bfloat16 l0 = __float2bfloat16(x.x - __bfloat162float(h0));
    __nv_bfloat16 l1 = __float2bfloat16(x.y - __bfloat162float(h1));
    __nv_bfloat16 l2 = __float2bfloat16(x.z - __bfloat162float(h2));
    __nv_bfloat16 l3 = __float2bfloat16(x.w - __bfloat162float(h3));

    size_t base = (size_t)m * 3 * K + k4;
    __nv_bfloat162 hA = __halves2bfloat162(h0, h1);
    __nv_bfloat162 hB = __halves2bfloat162(h2, h3);
    __nv_bfloat162 lA = __halves2bfloat162(l0, l1);
    __nv_bfloat162 lB = __halves2bfloat162(l2, l3);
    *(__nv_bfloat162*)(Aq + base)             = hA;
    *(__nv_bfloat162*)(Aq + base + 2)         = hB;
    *(__nv_bfloat162*)(Aq + base + K)         = hA;
    *(__nv_bfloat162*)(Aq + base + K + 2)     = hB;
    *(__nv_bfloat162*)(Aq + base + 2 * K)     = lA;
    *(__nv_bfloat162*)(Aq + base + 2 * K + 2) = lB;
}

// W [K,N] -> Wt bf16 [N, 3K] sections [hi, lo, hi]
__global__ void __launch_bounds__(256)
cvtW_k(const float* __restrict__ W, __nv_bfloat16* __restrict__ Wt,
       int K, int N, float scale)
{
    __shared__ float t[32][33];
    const int n0 = blockIdx.x * 32, k0 = blockIdx.y * 32;
    const int tx = threadIdx.x & 31, ty = threadIdx.x >> 5;
#pragma unroll
    for (int i = 0; i < 4; i++)
        t[ty + i * 8][tx] = W[(size_t)(k0 + ty + i * 8) * N + n0 + tx] * scale;
    __syncthreads();
    const int ld3 = 3 * K;
#pragma unroll
    for (int i = 0; i < 4; i++) {
        int n = n0 + ty + i * 8, k = k0 + tx;
        float v = t[tx][ty + i * 8];
        __nv_bfloat16 hi = __float2bfloat16(v);
        __nv_bfloat16 lo = __float2bfloat16(v - __bfloat162float(hi));
        size_t base = (size_t)n * ld3;
        Wt[base + k]         = hi;
        Wt[base + K + k]     = lo;
        Wt[base + 2 * K + k] = hi;
    }
}

// ====================== SIMT fp32 GEMM (attention only) ======================
template <int OP, bool TB>
__global__ void __launch_bounds__(256)
gemm_k(const float* __restrict__ A, const float* __restrict__ B,
       float* __restrict__ C,
       int M, int N, int K, int lda, int ldb, int ldc,
       long long sA1, long long sA2, int mA,
       long long sB1, long long sB2, int mB,
       long long sC1, long long sC2, int mC)
{
    const int z = blockIdx.z;
    A += (long long)(z / mA) * sA1 + (long long)(z % mA) * sA2;
    B += (long long)(z / mB) * sB1 + (long long)(z % mB) * sB2;
    C += (long long)(z / mC) * sC1 + (long long)(z % mC) * sC2;

    __shared__ float As[8][128];
    __shared__ float Bs[8][128];

    const int tid = threadIdx.x;
    const int tx  = tid & 15;
    const int ty  = tid >> 4;
    const int row0 = blockIdx.y * 128;
    const int col0 = blockIdx.x * 128;

    float acc[8][8];
#pragma unroll
    for (int i = 0; i < 8; i++)
#pragma unroll
        for (int j = 0; j < 8; j++) acc[i][j] = 0.f;

    for (int kt = 0; kt < K; kt += 8) {
#pragma unroll
        for (int i = 0; i < 4; i++) {
            int idx = i * 256 + tid;
            int r = idx >> 3, cc = idx & 7;
            int gr = row0 + r, gc = kt + cc;
            As[cc][r] = (gr < M && gc < K) ? A[(long long)gr * lda + gc] : 0.f;
        }
#pragma unroll
        for (int i = 0; i < 4; i++) {
            int idx = i * 256 + tid;
            int cc, n;
            if (TB) { n = idx >> 3; cc = idx & 7; }
            else    { cc = idx >> 7; n = idx & 127; }
            int gk = kt + cc, gn = col0 + n;
            float v = 0.f;
            if (gk < K && gn < N)
                v = TB ? B[(long long)gn * ldb + gk]
                       : B[(long long)gk * ldb + gn];
            Bs[cc][n] = v;
        }
        __syncthreads();
#pragma unroll
        for (int kk = 0; kk < 8; kk++) {
            float a[8], b[8];
#pragma unroll
            for (int i = 0; i < 8; i++) a[i] = As[kk][ty * 8 + i];
#pragma unroll
            for (int j = 0; j < 8; j++) b[j] = Bs[kk][tx * 8 + j];
#pragma unroll
            for (int i = 0; i < 8; i++)
#pragma unroll
                for (int j = 0; j < 8; j++) acc[i][j] = fmaf(a[i], b[j], acc[i][j]);
        }
        __syncthreads();
    }

#pragma unroll
    for (int i = 0; i < 8; i++) {
        int gr = row0 + ty * 8 + i;
        if (gr >= M) continue;
#pragma unroll
        for (int j = 0; j < 8; j++) {
            int gc = col0 + tx * 8 + j;
            if (gc >= N) continue;
            C[(long long)gr * ldc + gc] = acc[i][j];
        }
    }
}

// ====================== LayerNorm / softmax / embed ==========================
__global__ void __launch_bounds__(256)
ln_k(const float* __restrict__ X, const float* __restrict__ g,
     const float* __restrict__ b, float* __restrict__ Y)
{
    const long long row = blockIdx.x;
    const float* x = X + row * D;
    const int tid = threadIdx.x;
    float v[4];
    float s = 0.f;
#pragma unroll
    for (int i = 0; i < 4; i++) { v[i] = x[tid + i * 256]; s += v[i]; }

    __shared__ float red[256];
    red[tid] = s; __syncthreads();
    for (int o = 128; o > 0; o >>= 1) {
        if (tid < o) red[tid] += red[tid + o];
        __syncthreads();
    }
    const float mean = red[0] * (1.f / D);
    __syncthreads();

    float sq = 0.f;
#pragma unroll
    for (int i = 0; i < 4; i++) { float d0 = v[i] - mean; sq += d0 * d0; }
    red[tid] = sq; __syncthreads();
    for (int o = 128; o > 0; o >>= 1) {
        if (tid < o) red[tid] += red[tid + o];
        __syncthreads();
    }
    const float rstd = rsqrtf(red[0] * (1.f / D) + 1e-6f);

    float* y = Y + row * D;
#pragma unroll
    for (int i = 0; i < 4; i++) {
        int d0 = tid + i * 256;
        y[d0] = (v[i] - mean) * rstd * g[d0] + b[d0];
    }
}

__global__ void __launch_bounds__(256)
softmax_k(float* __restrict__ S)
{
    const int warp = (blockIdx.x * 256 + threadIdx.x) >> 5;
    const int lane = threadIdx.x & 31;
    const int nrows = BSZ * HEADS * NTOK;
    if (warp >= nrows) return;
    const int bh = warp / NTOK, r = warp % NTOK;
    float* p = S + (long long)bh * (NTOK * SLD) + (long long)r * SLD;

    float vals[9];
    float m = -1e30f;
#pragma unroll
    for (int i = 0; i < 9; i++) {
        int cc = lane + i * 32;
        vals[i] = (cc < NTOK) ? p[cc] : -1e30f;
        m = fmaxf(m, vals[i]);
    }
#pragma unroll
    for (int o = 16; o > 0; o >>= 1) m = fmaxf(m, __shfl_xor_sync(0xffffffffu, m, o));

    float s = 0.f;
#pragma unroll
    for (int i = 0; i < 9; i++) { vals[i] = expf(vals[i] - m); s += vals[i]; }
#pragma unroll
    for (int o = 16; o > 0; o >>= 1) s += __shfl_xor_sync(0xffffffffu, s, o);
    const float inv = 1.f / s;
#pragma unroll
    for (int i = 0; i < 9; i++) {
        int cc = lane + i * 32;
        if (cc < NTOK) p[cc] = vals[i] * inv;
    }
}

__global__ void __launch_bounds__(256)
patch_k(const float* __restrict__ x, const float* __restrict__ w,
        const float* __restrict__ cb, const float* __restrict__ pe,
        float* __restrict__ T)
{
    const int p  = blockIdx.x;
    const int b  = p >> 8, pp = p & 255;
    const int py = pp >> 4, px = pp & 15;
    const int tid = threadIdx.x;

    __shared__ float patch[48];
    if (tid < 48) {
        int ky = tid / 12, kx = (tid % 12) / 3, cc = tid % 3;
        patch[tid] = x[(((b * 64) + py * 4 + ky) * 64 + (px * 4 + kx)) * 3 + cc];
    }
    __syncthreads();

    float acc[4];
#pragma unroll
    for (int i = 0; i < 4; i++) acc[i] = cb[tid + i * 256];
#pragma unroll
    for (int k = 0; k < 48; k++) {
        float pk = patch[k];
#pragma unroll
        for (int i = 0; i < 4; i++)
            acc[i] = fmaf(pk, w[k * D + tid + i * 256], acc[i]);
    }
    long long base = ((long long)(b * NTOK + 1 + pp)) * D;
#pragma unroll
    for (int i = 0; i < 4; i++) {
        int d0 = tid + i * 256;
        T[base + d0] = acc[i] + pe[(long long)(1 + pp) * D + d0];
    }
}

__global__ void __launch_bounds__(256)
cls_k(const float* __restrict__ cls, const float* __restrict__ pe,
      float* __restrict__ T)
{
    const int b = blockIdx.x, tid = threadIdx.x;
#pragma unroll
    for (int i = 0; i < 4; i++) {
        int d0 = tid + i * 256;
        T[(long long)b * NTOK * D + d0] = cls[d0] + pe[d0];
    }
}

__global__ void __launch_bounds__(256)
out_k(const float* __restrict__ T, float* __restrict__ out)
{
    const int b = blockIdx.x, tid = threadIdx.x;
#pragma unroll
    for (int i = 0; i < 4; i++) {
        int d0 = tid + i * 256;
        out[(long long)b * D + d0] = T[(long long)b * NTOK * D + d0];
    }
}

// ====================== orchestration ========================================
extern "C" void kernel_launch(void* const* d_in, const int* in_sizes, int n_in,
                              void* d_out, int out_size)
{
    const float* x        = (const float*)d_in[0];
    const float* conv_w   = (const float*)d_in[1];
    const float* conv_b   = (const float*)d_in[2];
    const float* cls_tok  = (const float*)d_in[3];
    const float* pos_emb  = (const float*)d_in[4];
    const float* ln1_g    = (const float*)d_in[5];
    const float* ln1_b    = (const float*)d_in[6];
    const float* wq       = (const float*)d_in[7];
    const float* wk       = (const float*)d_in[8];
    const float* wv       = (const float*)d_in[9];
    const float* proj_w   = (const float*)d_in[10];
    const float* proj_b   = (const float*)d_in[11];
    const float* ln2_g    = (const float*)d_in[12];
    const float* ln2_b    = (const float*)d_in[13];
    const float* mlp1_w   = (const float*)d_in[14];
    const float* mlp1_b   = (const float*)d_in[15];
    const float* mlp2_w   = (const float*)d_in[16];
    const float* mlp2_b   = (const float*)d_in[17];
    float* out = (float*)d_out;

    float *t, *xn, *qkv, *y, *h, *s;
    __nv_bfloat16 *abf, *wbf;
    cudaGetSymbolAddress((void**)&t,   g_t);
    cudaGetSymbolAddress((void**)&xn,  g_xn);
    cudaGetSymbolAddress((void**)&qkv, g_qkv);
    cudaGetSymbolAddress((void**)&y,   g_y);
    cudaGetSymbolAddress((void**)&h,   g_h);
    cudaGetSymbolAddress((void**)&s,   g_s);
    cudaGetSymbolAddress((void**)&abf, g_abf);
    cudaGetSymbolAddress((void**)&wbf, g_wbf);

    cudaFuncSetAttribute(gemm_mma<0>, cudaFuncAttributeMaxDynamicSharedMemorySize, GEMM_SMEM);
    cudaFuncSetAttribute(gemm_mma<2>, cudaFuncAttributeMaxDynamicSharedMemorySize, GEMM_SMEM);
    cudaFuncSetAttribute(gemm_mma<3>, cudaFuncAttributeMaxDynamicSharedMemorySize, GEMM_SMEM);

    const float scale = 0.08838834764831845f;   // 128^-0.5

    // ---- weight conversion (split-bf16, transposed) ----
    for (int i = 0; i < LAYERS; i++) {
        __nv_bfloat16* wl = wbf + (size_t)i * W_LAYER;
        cvtW_k<<<dim3(D / 32, D / 32), 256>>>(wq + (size_t)i * D * D,
                                              wl + 0 * (size_t)3072, D, D, scale);
        cvtW_k<<<dim3(D / 32, D / 32), 256>>>(wk + (size_t)i * D * D,
                                              wl + (size_t)1024 * 3072, D, D, 1.f);
        cvtW_k<<<dim3(D / 32, D / 32), 256>>>(wv + (size_t)i * D * D,
                                              wl + (size_t)2048 * 3072, D, D, 1.f);
        cvtW_k<<<dim3(D / 32, D / 32), 256>>>(proj_w + (size_t)i * D * D,
                                              wl + W_PROJ, D, D, 1.f);
        cvtW_k<<<dim3(DF / 32, D / 32), 256>>>(mlp1_w + (size_t)i * D * DF,
                                               wl + W_M1, D, DF, 1.f);
        cvtW_k<<<dim3(D / 32, DF / 32), 256>>>(mlp2_w + (size_t)i * DF * D,
                                               wl + W_M2, DF, D, 1.f);
    }

    // ---- embed ----
    patch_k<<<BSZ * 256, 256>>>(x, conv_w, conv_b, pos_emb, t);
    cls_k<<<BSZ, 256>>>(cls_tok, pos_emb, t);

    const int Mt = (MTOK + 127) / 128;                 // 129
    const dim3 gQKV(3 * D / 128, Mt);                  // (24,129)
    const dim3 gD  (D / 128, Mt);                      // (8,129)
    const dim3 gDF (DF / 128, Mt);                     // (32,129)
    const dim3 gS  ((NTOK + 127) / 128, (NTOK + 127) / 128, BSZ * HEADS);
    const dim3 gY  (1, (NTOK + 127) / 128, BSZ * HEADS);
    const long long cvD = (long long)MTOK * D / 4;
    const long long cvF = (long long)MTOK * DF / 4;

    for (int i = 0; i < LAYERS; i++) {
        const __nv_bfloat16* wl = wbf + (size_t)i * W_LAYER;
        const float* pb_i = proj_b + (size_t)i * D;
        const float* m1b  = mlp1_b + (size_t)i * DF;
        const float* m2b  = mlp2_b + (size_t)i * D;

        ln_k<<<MTOK, 256>>>(t, ln1_g + (size_t)i * D, ln1_b + (size_t)i * D, xn);
        cvtA_k<<<(unsigned)((cvD + 255) / 256), 256>>>(xn, abf, D, cvD);

        // fused QKV (q-scale folded into weights)
        gemm_mma<0><<<gQKV, 256, GEMM_SMEM>>>(abf, wl + W_QKV, nullptr, nullptr,
                                              qkv, MTOK, 3 * D, K3D, 3 * D);

        // scores = q @ k^T
        gemm_k<0, true><<<gS, 256>>>(qkv, qkv + 1024, s,
            NTOK, NTOK, HD, 3 * D, 3 * D, SLD,
            (long long)NTOK * 3 * D, HD, HEADS,
            (long long)NTOK * 3 * D, HD, HEADS,
            (long long)NTOK * SLD, 0, 1);

        softmax_k<<<(BSZ * HEADS * NTOK + 7) / 8, 256>>>(s);

        // y = attn @ v
        gemm_k<0, false><<<gY, 256>>>(s, qkv + 2048, y,
            NTOK, HD, NTOK, SLD, 3 * D, D,
            (long long)NTOK * SLD, 0, 1,
            (long long)NTOK * 3 * D, HD, HEADS,
            (long long)NTOK * D, HD, HEADS);

        // t += y @ proj_w + proj_b
        cvtA_k<<<(unsigned)((cvD + 255) / 256), 256>>>(y, abf, D, cvD);
        gemm_mma<2><<<gD, 256, GEMM_SMEM>>>(abf, wl + W_PROJ, pb_i, t,
                                            t, MTOK, D, K3D, D);

        ln_k<<<MTOK, 256>>>(t, ln2_g + (size_t)i * D, ln2_b + (size_t)i * D, xn);
        cvtA_k<<<(unsigned)((cvD + 255) / 256), 256>>>(xn, abf, D, cvD);

        // h = gelu(xn @ mlp1_w + b)
        gemm_mma<3><<<gDF, 256, GEMM_SMEM>>>(abf, wl + W_M1, m1b, nullptr,
                                             h, MTOK, DF, K3D, DF);

        // t += h @ mlp2_w + b
        cvtA_k<<<(unsigned)((cvF + 255) / 256), 256>>>(h, abf, DF, cvF);
        gemm_mma<2><<<gD, 256, GEMM_SMEM>>>(abf, wl + W_M2, m2b, t,
                                            t, MTOK, D, K3F, D);
    }

    out_k<<<BSZ, 256>>>(t, out);
}

// round 5
// speedup vs baseline: 3.9355x; 1.2437x over previous
#include <cuda_runtime.h>
#include <cuda_bf16.h>
#include <cstdint>
#include <math.h>

#define D      1024
#define DF     4096
#define NTOK   257
#define BSZ    64
#define LAYERS 8
#define HEADS  8
#define HD     128
#define MTOK   (BSZ * NTOK)      /* 16448 */
#define BH     (BSZ * HEADS)     /* 512 */
#define SLD    384               /* scores leading dim (padded) */
#define KATT   320               /* attn@v K padded (257 -> 320) */

// 2-section split widths
#define QK_ROWS 384              /* padded token rows per (b,h) */
#define QKOFF   ((long long)BH * QK_ROWS * 256)

// per-layer bf16 weight offsets (elements), 2-section [hi|lo] rows
#define W_QKV   0LL
#define W_PROJ  (3072LL * 2048)                  /* 6291456  */
#define W_M1    (W_PROJ + 1024LL * 2048)         /* 8388608  */
#define W_M2    (W_M1  + 4096LL * 2048)          /* 16777216 */
#define W_LAYER (W_M2  + 1024LL * 8192)          /* 25165824 */

// ---------------- scratch (device globals) ----------------------------------
__device__ float g_t  [MTOK * D];
__device__ float g_qkv[(size_t)MTOK * 3 * D];
__device__ float g_s  [(size_t)BH * NTOK * SLD];
__device__ __align__(16) __nv_bfloat16 g_a2 [(size_t)MTOK * 2 * D];
__device__ __align__(16) __nv_bfloat16 g_abf[(size_t)MTOK * 2 * DF];
__device__ __align__(16) __nv_bfloat16 g_qk [(size_t)2 * BH * QK_ROWS * 256];
__device__ __align__(16) __nv_bfloat16 g_vt [(size_t)BH * HD * (2 * KATT)];
__device__ __align__(16) __nv_bfloat16 g_at [(size_t)BH * NTOK * (2 * KATT)];
__device__ __align__(16) __nv_bfloat16 g_wbf[(size_t)LAYERS * W_LAYER];

// ============================ PTX helpers ====================================
__device__ __forceinline__ uint32_t smem_u32(const void* p) {
    uint32_t a;
    asm("{ .reg .u64 t; cvta.to.shared.u64 t, %1; cvt.u32.u64 %0, t; }"
        : "=r"(a) : "l"(p));
    return a;
}
__device__ __forceinline__ void cpasync16(uint32_t s, const void* g, uint32_t sz) {
    asm volatile("cp.async.cg.shared.global [%0], [%1], 16, %2;"
                 :: "r"(s), "l"(g), "r"(sz) : "memory");
}
__device__ __forceinline__ void ldsm4(uint32_t& r0, uint32_t& r1,
                                      uint32_t& r2, uint32_t& r3, uint32_t a) {
    asm volatile("ldmatrix.sync.aligned.m8n8.x4.shared.b16 {%0,%1,%2,%3}, [%4];"
                 : "=r"(r0), "=r"(r1), "=r"(r2), "=r"(r3) : "r"(a));
}
__device__ __forceinline__ void mma16816(float* d, const uint32_t* a,
                                         const uint32_t* b) {
    asm volatile("mma.sync.aligned.m16n8k16.row.col.f32.bf16.bf16.f32 "
                 "{%0,%1,%2,%3}, {%4,%5,%6,%7}, {%8,%9}, {%0,%1,%2,%3};"
                 : "+f"(d[0]), "+f"(d[1]), "+f"(d[2]), "+f"(d[3])
                 : "r"(a[0]), "r"(a[1]), "r"(a[2]), "r"(a[3]),
                   "r"(b[0]), "r"(b[1]));
}
__device__ __forceinline__ __nv_bfloat162 split_hi2(float a, float b,
                                                    __nv_bfloat162& lo) {
    __nv_bfloat16 h0 = __float2bfloat16(a), h1 = __float2bfloat16(b);
    lo = __halves2bfloat162(__float2bfloat16(a - __bfloat162float(h0)),
                            __float2bfloat16(b - __bfloat162float(h1)));
    return __halves2bfloat162(h0, h1);
}

// ====================== HMMA split-bf16 GEMM =================================
// Logical: C[M,N] = A[M,K] @ Bt[N,K]^T in near-fp32 via 3 bf16 products.
// Storage: A rows = [Ah(K) | Al(K)] (2K wide), Bt rows = [Bh(K) | Bl(K)].
// phase 0: Ah*Bh, 1: Ah*Bl, 2: Al*Bh
// EPI: 0 = fp32 C          2 = fp32 C = . + bias + Res
//      4 = split bf16 Cs = gelu(. + bias)    5 = split bf16 Cs = .
#define STG_BYTES 32768
#define GEMM_SMEM (3 * STG_BYTES)

template <int EPI>
__global__ void __launch_bounds__(256, 2)
gemm_mma(const __nv_bfloat16* __restrict__ A, const __nv_bfloat16* __restrict__ Bw,
         const float* __restrict__ bias, const float* __restrict__ Res,
         float* __restrict__ C, __nv_bfloat16* __restrict__ Cs,
         int M, int K, int ldc, int splitoff,
         long long sA1, long long sA2, int mA,
         long long sB1, long long sB2, int mB,
         long long sC1, long long sC2, int mC)
{
    extern __shared__ char smem[];
    const uint32_t sb = smem_u32(smem);
    const int tid  = threadIdx.x;
    const int wid  = tid >> 5, lane = tid & 31;
    const int wm   = wid & 1, wn = wid >> 1;       // 2 x 4 warp grid
    const int row0 = blockIdx.y * 128, col0 = blockIdx.x * 128;

    const int z = blockIdx.z;
    A  += (long long)(z / mA) * sA1 + (long long)(z % mA) * sA2;
    Bw += (long long)(z / mB) * sB1 + (long long)(z % mB) * sB2;
    const long long coff = (long long)(z / mC) * sC1 + (long long)(z % mC) * sC2;
    if (EPI == 0 || EPI == 2) C  += coff;
    if (EPI == 2)             Res += coff;
    if (EPI >= 4)             Cs += coff;

    const long long rowBy = 4LL * K;               // bytes per stored row (2K bf16)

    const int ldrow = tid >> 3, ldch = tid & 7;
    const char* gA = (const char*)A  + (long long)(row0 + ldrow) * rowBy + ldch * 16;
    const char* gB = (const char*)Bw + (long long)(col0 + ldrow) * rowBy + ldch * 16;

    auto load_stage = [&](int kt) {
        const uint32_t st = sb + (kt % 3) * STG_BYTES;
        const int phase = kt % 3, kc = kt / 3;
        const long long offA = (long long)(((phase == 2) ? K : 0) + kc * 64) * 2;
        const long long offB = (long long)(((phase == 1) ? K : 0) + kc * 64) * 2;
#pragma unroll
        for (int i = 0; i < 4; i++) {
            int r = i * 32 + ldrow;
            uint32_t off = (uint32_t)(r * 128 + ((ldch ^ (r & 7)) * 16));
            uint32_t szA = (row0 + r < M) ? 16u : 0u;
            const char* a = szA ? (gA + (long long)i * 32 * rowBy + offA)
                                : (const char*)A;
            cpasync16(st + off, a, szA);
            cpasync16(st + 16384 + off, gB + (long long)i * 32 * rowBy + offB, 16u);
        }
        asm volatile("cp.async.commit_group;" ::: "memory");
    };

    const int grp = lane >> 3, l8 = lane & 7;
    const int aRowB = wm * 64 + (grp & 1) * 8 + l8;
    const int aCG   = grp >> 1;
    const int bRowB = wn * 32 + (grp >> 1) * 8 + l8;
    const int bCG   = grp & 1;

    float acc[4][4][4];
#pragma unroll
    for (int i = 0; i < 4; i++)
#pragma unroll
        for (int j = 0; j < 4; j++)
#pragma unroll
            for (int r = 0; r < 4; r++) acc[i][j][r] = 0.f;

    const int nkt = 3 * (K / 64);
    load_stage(0);
    load_stage(1);

    for (int kt = 0; kt < nkt; kt++) {
        asm volatile("cp.async.wait_group 1;" ::: "memory");
        __syncthreads();
        if (kt + 2 < nkt) load_stage(kt + 2);
        else asm volatile("cp.async.commit_group;" ::: "memory");

        const uint32_t sA = sb + (kt % 3) * STG_BYTES;
        const uint32_t sB = sA + 16384;

#pragma unroll
        for (int ks = 0; ks < 4; ks++) {
            uint32_t af[4][4], bf2[2][4];
            const uint32_t aSw = (uint32_t)(((ks * 2 + aCG) ^ l8) * 16);
            const uint32_t bSw = (uint32_t)(((ks * 2 + bCG) ^ l8) * 16);
#pragma unroll
            for (int mi = 0; mi < 4; mi++)
                ldsm4(af[mi][0], af[mi][1], af[mi][2], af[mi][3],
                      sA + (uint32_t)((aRowB + mi * 16) * 128) + aSw);
#pragma unroll
            for (int ni2 = 0; ni2 < 2; ni2++)
                ldsm4(bf2[ni2][0], bf2[ni2][1], bf2[ni2][2], bf2[ni2][3],
                      sB + (uint32_t)((bRowB + ni2 * 16) * 128) + bSw);
#pragma unroll
            for (int mi = 0; mi < 4; mi++)
#pragma unroll
                for (int ni = 0; ni < 4; ni++)
                    mma16816(acc[mi][ni], af[mi], &bf2[ni >> 1][(ni & 1) * 2]);
        }
    }

    // ---- epilogue ----
#pragma unroll
    for (int mi = 0; mi < 4; mi++) {
#pragma unroll
        for (int ni = 0; ni < 4; ni++) {
            float* c = acc[mi][ni];
            int m0 = row0 + wm * 64 + mi * 16 + (lane >> 2);
            int n  = col0 + wn * 32 + ni * 8 + (lane & 3) * 2;
            float b0 = 0.f, b1 = 0.f;
            if (EPI == 2 || EPI == 4) { b0 = bias[n]; b1 = bias[n + 1]; }
#pragma unroll
            for (int half = 0; half < 2; half++) {
                int m = m0 + half * 8;
                if (m >= M) continue;
                float v0 = c[half * 2 + 0], v1 = c[half * 2 + 1];
                if (EPI == 2) {
                    const float* rp = Res + (size_t)m * ldc + n;
                    v0 += b0 + rp[0]; v1 += b1 + rp[1];
                }
                if (EPI == 4) {
                    v0 += b0; v1 += b1;
                    v0 = 0.5f * v0 * (1.f + erff(v0 * 0.7071067811865475f));
                    v1 = 0.5f * v1 * (1.f + erff(v1 * 0.7071067811865475f));
                }
                if (EPI == 0 || EPI == 2) {
                    *(float2*)(C + (size_t)m * ldc + n) = make_float2(v0, v1);
                } else {
                    __nv_bfloat162 lo;
                    __nv_bfloat162 hi = split_hi2(v0, v1, lo);
                    *(__nv_bfloat162*)(Cs + (size_t)m * ldc + n)            = hi;
                    *(__nv_bfloat162*)(Cs + (size_t)m * ldc + splitoff + n) = lo;
                }
            }
        }
    }
}

// ====================== conversions ==========================================
// W [K,N] fp32 -> Wt bf16 [N, 2K] = [hi | lo]
__global__ void __launch_bounds__(256)
cvtW_k(const float* __restrict__ W, __nv_bfloat16* __restrict__ Wt,
       int K, int N, float scale)
{
    __shared__ float t[32][33];
    const int n0 = blockIdx.x * 32, k0 = blockIdx.y * 32;
    const int tx = threadIdx.x & 31, ty = threadIdx.x >> 5;
#pragma unroll
    for (int i = 0; i < 4; i++)
        t[ty + i * 8][tx] = W[(size_t)(k0 + ty + i * 8) * N + n0 + tx] * scale;
    __syncthreads();
#pragma unroll
    for (int i = 0; i < 4; i++) {
        int n = n0 + ty + i * 8, k = k0 + tx;
        float v = t[tx][ty + i * 8];
        __nv_bfloat16 hi = __float2bfloat16(v);
        __nv_bfloat16 lo = __float2bfloat16(v - __bfloat162float(hi));
        size_t base = (size_t)n * 2 * K;
        Wt[base + k]     = hi;
        Wt[base + K + k] = lo;
    }
}

// qkv fp32 [MTOK,3072] (q,k cols) -> split per-head rows [bh, tok, 256]
__global__ void __launch_bounds__(256)
cvtQK_k(const float* __restrict__ QKV, __nv_bfloat16* __restrict__ QK)
{
    long long i = (long long)blockIdx.x * 256 + threadIdx.x;
    if (i >= (long long)MTOK * 512) return;
    int m = (int)(i >> 9);
    int n4 = ((int)i & 511) * 4;
    int sec = n4 >> 10, h = (n4 & 1023) >> 7, hd = n4 & 127;
    float4 x = *(const float4*)(QKV + (size_t)m * 3072 + n4);
    int b = m / NTOK, tok = m % NTOK;
    __nv_bfloat16* dst = QK + sec * QKOFF
                       + ((long long)(b * HEADS + h) * QK_ROWS + tok) * 256 + hd;
    __nv_bfloat162 loA, loB;
    __nv_bfloat162 hiA = split_hi2(x.x, x.y, loA);
    __nv_bfloat162 hiB = split_hi2(x.z, x.w, loB);
    *(__nv_bfloat162*)(dst)           = hiA;
    *(__nv_bfloat162*)(dst + 2)       = hiB;
    *(__nv_bfloat162*)(dst + 128)     = loA;
    *(__nv_bfloat162*)(dst + 128 + 2) = loB;
}

// qkv v-section -> vT split [bh, hd(128), 2*KATT] with zero pad tok>=257
__global__ void __launch_bounds__(256)
cvtVT_k(const float* __restrict__ QKV, __nv_bfloat16* __restrict__ VT)
{
    const int bh = blockIdx.x, tt = blockIdx.y, ht = blockIdx.z;
    const int b = bh >> 3, h = bh & 7;
    const int tx = threadIdx.x & 31, ty = threadIdx.x >> 5;
    __shared__ float t[32][33];
#pragma unroll
    for (int j = 0; j < 4; j++) {
        int tok = tt * 32 + ty + j * 8;
        int hd  = ht * 32 + tx;
        float v = 0.f;
        if (tok < NTOK)
            v = QKV[((size_t)(b * NTOK + tok)) * 3072 + 2048 + h * 128 + hd];
        t[ty + j * 8][tx] = v;
    }
    __syncthreads();
#pragma unroll
    for (int j = 0; j < 4; j++) {
        int hd  = ht * 32 + ty + j * 8;
        int tok = tt * 32 + tx;
        float v = t[tx][ty + j * 8];
        __nv_bfloat16 hi = __float2bfloat16(v);
        __nv_bfloat16 lo = __float2bfloat16(v - __bfloat162float(hi));
        __nv_bfloat16* dst = VT + ((size_t)bh * HD + hd) * (2 * KATT) + tok;
        dst[0]    = hi;
        dst[KATT] = lo;
    }
}

// softmax over scores rows + write split-bf16 probs (zero pad to KATT)
__global__ void __launch_bounds__(256)
softmax_split_k(const float* __restrict__ S, __nv_bfloat16* __restrict__ AT)
{
    const int warp = (blockIdx.x * 256 + threadIdx.x) >> 5;
    const int lane = threadIdx.x & 31;
    if (warp >= BH * NTOK) return;
    const float* p = S + (size_t)warp * SLD;

    float vals[10];
    float m = -1e30f;
#pragma unroll
    for (int i = 0; i < 10; i++) {
        int c = lane + i * 32;
        vals[i] = (c < NTOK) ? p[c] : -1e30f;
        m = fmaxf(m, vals[i]);
    }
#pragma unroll
    for (int o = 16; o > 0; o >>= 1) m = fmaxf(m, __shfl_xor_sync(0xffffffffu, m, o));
    float s = 0.f;
#pragma unroll
    for (int i = 0; i < 10; i++) { vals[i] = expf(vals[i] - m); s += vals[i]; }
#pragma unroll
    for (int o = 16; o > 0; o >>= 1) s += __shfl_xor_sync(0xffffffffu, s, o);
    const float inv = 1.f / s;

    __nv_bfloat16* q = AT + (size_t)warp * (2 * KATT);
#pragma unroll
    for (int i = 0; i < 10; i++) {
        int c = lane + i * 32;
        float v = vals[i] * inv;
        __nv_bfloat16 hi = __float2bfloat16(v);
        __nv_bfloat16 lo = __float2bfloat16(v - __bfloat162float(hi));
        q[c]        = hi;
        q[KATT + c] = lo;
    }
}

// LayerNorm -> split-bf16 [m, 2D]
__global__ void __launch_bounds__(256)
ln_split_k(const float* __restrict__ X, const float* __restrict__ g,
           const float* __restrict__ b, __nv_bfloat16* __restrict__ Y)
{
    const long long row = blockIdx.x;
    const float* x = X + row * D;
    const int tid = threadIdx.x;
    float v[4];
    float s = 0.f;
#pragma unroll
    for (int i = 0; i < 4; i++) { v[i] = x[tid + i * 256]; s += v[i]; }

    __shared__ float red[256];
    red[tid] = s; __syncthreads();
    for (int o = 128; o > 0; o >>= 1) {
        if (tid < o) red[tid] += red[tid + o];
        __syncthreads();
    }
    const float mean = red[0] * (1.f / D);
    __syncthreads();
    float sq = 0.f;
#pragma unroll
    for (int i = 0; i < 4; i++) { float d0 = v[i] - mean; sq += d0 * d0; }
    red[tid] = sq; __syncthreads();
    for (int o = 128; o > 0; o >>= 1) {
        if (tid < o) red[tid] += red[tid + o];
        __syncthreads();
    }
    const float rstd = rsqrtf(red[0] * (1.f / D) + 1e-6f);

    __nv_bfloat16* y = Y + row * 2 * D;
#pragma unroll
    for (int i = 0; i < 4; i++) {
        int d0 = tid + i * 256;
        float val = (v[i] - mean) * rstd * g[d0] + b[d0];
        __nv_bfloat16 hi = __float2bfloat16(val);
        y[d0]     = hi;
        y[D + d0] = __float2bfloat16(val - __bfloat162float(hi));
    }
}

// ====================== embed / out ==========================================
__global__ void __launch_bounds__(256)
patch_k(const float* __restrict__ x, const float* __restrict__ w,
        const float* __restrict__ cb, const float* __restrict__ pe,
        float* __restrict__ T)
{
    const int p  = blockIdx.x;
    const int b  = p >> 8, pp = p & 255;
    const int py = pp >> 4, px = pp & 15;
    const int tid = threadIdx.x;

    __shared__ float patch[48];
    if (tid < 48) {
        int ky = tid / 12, kx = (tid % 12) / 3, cc = tid % 3;
        patch[tid] = x[(((b * 64) + py * 4 + ky) * 64 + (px * 4 + kx)) * 3 + cc];
    }
    __syncthreads();

    float acc[4];
#pragma unroll
    for (int i = 0; i < 4; i++) acc[i] = cb[tid + i * 256];
#pragma unroll
    for (int k = 0; k < 48; k++) {
        float pk = patch[k];
#pragma unroll
        for (int i = 0; i < 4; i++)
            acc[i] = fmaf(pk, w[k * D + tid + i * 256], acc[i]);
    }
    long long base = ((long long)(b * NTOK + 1 + pp)) * D;
#pragma unroll
    for (int i = 0; i < 4; i++) {
        int d0 = tid + i * 256;
        T[base + d0] = acc[i] + pe[(long long)(1 + pp) * D + d0];
    }
}

__global__ void __launch_bounds__(256)
cls_k(const float* __restrict__ cls, const float* __restrict__ pe,
      float* __restrict__ T)
{
    const int b = blockIdx.x, tid = threadIdx.x;
#pragma unroll
    for (int i = 0; i < 4; i++) {
        int d0 = tid + i * 256;
        T[(long long)b * NTOK * D + d0] = cls[d0] + pe[d0];
    }
}

__global__ void __launch_bounds__(256)
out_k(const float* __restrict__ T, float* __restrict__ out)
{
    const int b = blockIdx.x, tid = threadIdx.x;
#pragma unroll
    for (int i = 0; i < 4; i++) {
        int d0 = tid + i * 256;
        out[(long long)b * D + d0] = T[(long long)b * NTOK * D + d0];
    }
}

// ====================== orchestration ========================================
extern "C" void kernel_launch(void* const* d_in, const int* in_sizes, int n_in,
                              void* d_out, int out_size)
{
    const float* x        = (const float*)d_in[0];
    const float* conv_w   = (const float*)d_in[1];
    const float* conv_b   = (const float*)d_in[2];
    const float* cls_tok  = (const float*)d_in[3];
    const float* pos_emb  = (const float*)d_in[4];
    const float* ln1_g    = (const float*)d_in[5];
    const float* ln1_b    = (const float*)d_in[6];
    const float* wq       = (const float*)d_in[7];
    const float* wk       = (const float*)d_in[8];
    const float* wv       = (const float*)d_in[9];
    const float* proj_w   = (const float*)d_in[10];
    const float* proj_b   = (const float*)d_in[11];
    const float* ln2_g    = (const float*)d_in[12];
    const float* ln2_b    = (const float*)d_in[13];
    const float* mlp1_w   = (const float*)d_in[14];
    const float* mlp1_b   = (const float*)d_in[15];
    const float* mlp2_w   = (const float*)d_in[16];
    const float* mlp2_b   = (const float*)d_in[17];
    float* out = (float*)d_out;

    float *t, *qkv, *s;
    __nv_bfloat16 *a2, *abf, *qk, *vt, *at, *wbf;
    cudaGetSymbolAddress((void**)&t,   g_t);
    cudaGetSymbolAddress((void**)&qkv, g_qkv);
    cudaGetSymbolAddress((void**)&s,   g_s);
    cudaGetSymbolAddress((void**)&a2,  g_a2);
    cudaGetSymbolAddress((void**)&abf, g_abf);
    cudaGetSymbolAddress((void**)&qk,  g_qk);
    cudaGetSymbolAddress((void**)&vt,  g_vt);
    cudaGetSymbolAddress((void**)&at,  g_at);
    cudaGetSymbolAddress((void**)&wbf, g_wbf);

    cudaFuncSetAttribute(gemm_mma<0>, cudaFuncAttributeMaxDynamicSharedMemorySize, GEMM_SMEM);
    cudaFuncSetAttribute(gemm_mma<2>, cudaFuncAttributeMaxDynamicSharedMemorySize, GEMM_SMEM);
    cudaFuncSetAttribute(gemm_mma<4>, cudaFuncAttributeMaxDynamicSharedMemorySize, GEMM_SMEM);
    cudaFuncSetAttribute(gemm_mma<5>, cudaFuncAttributeMaxDynamicSharedMemorySize, GEMM_SMEM);

    const float scale = 0.08838834764831845f;   // 128^-0.5

    // ---- weight conversion ----
    for (int i = 0; i < LAYERS; i++) {
        __nv_bfloat16* wl = wbf + (size_t)i * W_LAYER;
        cvtW_k<<<dim3(D / 32, D / 32), 256>>>(wq + (size_t)i * D * D, wl, D, D, scale);
        cvtW_k<<<dim3(D / 32, D / 32), 256>>>(wk + (size_t)i * D * D,
                                              wl + 1024LL * 2048, D, D, 1.f);
        cvtW_k<<<dim3(D / 32, D / 32), 256>>>(wv + (size_t)i * D * D,
                                              wl + 2048LL * 2048, D, D, 1.f);
        cvtW_k<<<dim3(D / 32, D / 32), 256>>>(proj_w + (size_t)i * D * D,
                                              wl + W_PROJ, D, D, 1.f);
        cvtW_k<<<dim3(DF / 32, D / 32), 256>>>(mlp1_w + (size_t)i * D * DF,
                                               wl + W_M1, D, DF, 1.f);
        cvtW_k<<<dim3(D / 32, DF / 32), 256>>>(mlp2_w + (size_t)i * DF * D,
                                               wl + W_M2, DF, D, 1.f);
    }

    // ---- embed ----
    patch_k<<<BSZ * 256, 256>>>(x, conv_w, conv_b, pos_emb, t);
    cls_k<<<BSZ, 256>>>(cls_tok, pos_emb, t);

    const int Mt = (MTOK + 127) / 128;                 // 129
    const dim3 gQKV(24, Mt);
    const dim3 gD  (8, Mt);
    const dim3 gDF (32, Mt);
    const dim3 gS  (3, 3, BH);
    const dim3 gY  (1, 3, BH);

    for (int i = 0; i < LAYERS; i++) {
        const __nv_bfloat16* wl = wbf + (size_t)i * W_LAYER;
        const float* pb_i = proj_b + (size_t)i * D;
        const float* m1b  = mlp1_b + (size_t)i * DF;
        const float* m2b  = mlp2_b + (size_t)i * D;

        // LN1 -> split
        ln_split_k<<<MTOK, 256>>>(t, ln1_g + (size_t)i * D, ln1_b + (size_t)i * D, a2);

        // QKV: qkv fp32 (scale folded into wq)
        gemm_mma<0><<<gQKV, 256, GEMM_SMEM>>>(a2, wl, nullptr, nullptr, qkv, nullptr,
            MTOK, D, 3 * D, 0, 0, 0, 1, 0, 0, 1, 0, 0, 1);

        cvtQK_k<<<(unsigned)(((long long)MTOK * 512 + 255) / 256), 256>>>(qkv, qk);
        cvtVT_k<<<dim3(BH, KATT / 32, HD / 32), 256>>>(qkv, vt);

        // scores = q @ k^T  (per b,h)
        gemm_mma<0><<<gS, 256, GEMM_SMEM>>>(qk, qk + QKOFF, nullptr, nullptr, s, nullptr,
            NTOK, HD, SLD, 0,
            (long long)QK_ROWS * 256, 0, 1,
            (long long)QK_ROWS * 256, 0, 1,
            (long long)NTOK * SLD, 0, 1);

        softmax_split_k<<<(BH * NTOK + 7) / 8, 256>>>(s, at);

        // y = attn @ v -> split bf16 into a2 [tok, 2D] laid out by (b,h)
        gemm_mma<5><<<gY, 256, GEMM_SMEM>>>(at, vt, nullptr, nullptr, nullptr, a2,
            NTOK, KATT, 2 * D, D,
            (long long)NTOK * 2 * KATT, 0, 1,
            (long long)HD * 2 * KATT, 0, 1,
            (long long)NTOK * 2 * D, HD, HEADS);

        // t += y @ proj_w + proj_b
        gemm_mma<2><<<gD, 256, GEMM_SMEM>>>(a2, wl + W_PROJ, pb_i, t, t, nullptr,
            MTOK, D, D, 0, 0, 0, 1, 0, 0, 1, 0, 0, 1);

        // LN2 -> split
        ln_split_k<<<MTOK, 256>>>(t, ln2_g + (size_t)i * D, ln2_b + (size_t)i * D, a2);

        // h = gelu(xn @ mlp1_w + b) -> split bf16
        gemm_mma<4><<<gDF, 256, GEMM_SMEM>>>(a2, wl + W_M1, m1b, nullptr, nullptr, abf,
            MTOK, D, 2 * DF, DF, 0, 0, 1, 0, 0, 1, 0, 0, 1);

        // t += h @ mlp2_w + b
        gemm_mma<2><<<gD, 256, GEMM_SMEM>>>(abf, wl + W_M2, m2b, t, t, nullptr,
            MTOK, DF, D, 0, 0, 0, 1, 0, 0, 1, 0, 0, 1);
    }

    out_k<<<BSZ, 256>>>(t, out);
}